// round 17
// baseline (speedup 1.0000x reference)
#include <cuda_runtime.h>
#include <cuda_bf16.h>
#include <cstdint>

#define B_  64
#define IC  512
#define ID  128
#define NC  32
#define DC  32
#define TI  128
#define NBLK 256
#define CLUSTER 4

#define CST 36      // fp32 cs row stride (floats)
#define BFS 136     // bf16 row stride (elements)
#define YST 132     // Ysm / Yred fp32 row stride (floats)

// byte offsets in dynamic smem
#define CS_OFF   0                       // fp32 cs [128][36] = 18432 (alias: Ysm [32][132] fp32)
#define XSB_OFF  18432                   // bf16 xs_hi [128][136] = 34816 (iter2: xsT_lo)
#define XTB_OFF  53248                   // bf16 xsT_hi [128][136] = 34816
#define WVB_OFF  88064                   // bf16 wv [32][136] = 8704
#define CTH_OFF  96768                   // bf16 cT_hi [32][136] = 8704
#define CTL_OFF  105472                  // bf16 cT_lo [32][136] = 8704 (alias: Yred[8][132]f32 + vsm[8][32]f32)
#define SMEM_BYTES 114176                // 111.5 KB -> 2 CTA/SM

// ---- helpers ----
__device__ __forceinline__ uint32_t smem_u32(const void* p) {
    uint32_t a;
    asm("{ .reg .u64 t; cvta.to.shared.u64 t, %1; cvt.u32.u64 %0, t; }" : "=r"(a) : "l"(p));
    return a;
}
__device__ __forceinline__ uint32_t cvt2(float lo, float hi) {
    uint32_t r;
    asm("cvt.rn.bf16x2.f32 %0, %1, %2;" : "=r"(r) : "f"(hi), "f"(lo));
    return r;
}
__device__ __forceinline__ float fexp(float x) {   // Schraudolph fast exp (routing iters only)
    return __int_as_float((int)fmaf(x, 12102203.0f, 1064986816.0f));
}
__device__ __forceinline__ uint32_t mapa_u32(uint32_t a, uint32_t rk) {
    uint32_t r;
    asm("mapa.shared::cluster.u32 %0, %1, %2;" : "=r"(r) : "r"(a), "r"(rk));
    return r;
}
__device__ __forceinline__ float4 ld_dsmem4(uint32_t a) {
    float4 v;
    asm volatile("ld.shared::cluster.v4.f32 {%0,%1,%2,%3}, [%4];"
                 : "=f"(v.x), "=f"(v.y), "=f"(v.z), "=f"(v.w) : "r"(a));
    return v;
}
__device__ __forceinline__ uint32_t ld_dsmem1(uint32_t a) {
    uint32_t v;
    asm volatile("ld.shared::cluster.b32 %0, [%1];" : "=r"(v) : "r"(a));
    return v;
}
#define CLUSTER_SYNC() do { \
    asm volatile("barrier.cluster.arrive.aligned;" ::: "memory"); \
    asm volatile("barrier.cluster.wait.aligned;" ::: "memory"); \
} while (0)

__device__ __forceinline__ void ldsm_x4(uint32_t& r0, uint32_t& r1, uint32_t& r2,
                                        uint32_t& r3, uint32_t addr) {
    asm volatile("ldmatrix.sync.aligned.m8n8.x4.shared.b16 {%0,%1,%2,%3}, [%4];"
                 : "=r"(r0), "=r"(r1), "=r"(r2), "=r"(r3) : "r"(addr));
}
__device__ __forceinline__ void mma_bf16(float* d, uint32_t a0, uint32_t a1,
                                         uint32_t a2, uint32_t a3,
                                         uint32_t b0, uint32_t b1) {
    asm volatile(
        "mma.sync.aligned.m16n8k16.row.col.f32.bf16.bf16.f32 "
        "{%0,%1,%2,%3}, {%4,%5,%6,%7}, {%8,%9}, {%0,%1,%2,%3};"
        : "+f"(d[0]), "+f"(d[1]), "+f"(d[2]), "+f"(d[3])
        : "r"(a0), "r"(a1), "r"(a2), "r"(a3), "r"(b0), "r"(b1));
}

// ============================================================
// Cluster mega-kernel: cluster (4 CTAs) = one batch; rank = i-tile.
// Y partials + wv exchanged via DSMEM; no grid-wide sync, no
// device scratch, no persistence requirement.
// ============================================================
__global__ __launch_bounds__(256, 2) __cluster_dims__(CLUSTER, 1, 1)
void k_mega(
    const float* __restrict__ X,
    const float* __restrict__ W,
    const float* __restrict__ B0,
    float* __restrict__ OUT)
{
    extern __shared__ __align__(16) char smc[];
    float* cs = (float*)(smc + CS_OFF);
    const uint32_t smb = smem_u32(smc);

    const int blk  = blockIdx.x;
    const int b    = blk >> 2;          // cluster id = batch
    const int tt   = blk & 3;           // rank in cluster = i-tile
    const int i0   = tt * TI;
    const int t    = threadIdx.x;
    const int lane = t & 31;
    const int w    = t >> 5;
    const int m0   = w * 16;

    // fragment address lane maps
    const int a_row = m0 + (lane & 15);
    const int a_col = (lane >> 4) << 3;
    const int b_row = (lane & 7) + ((lane >> 4) << 3);
    const int b_col = ((lane >> 3) & 1) << 3;

    const uint32_t aXS_base = smb + XSB_OFF + (uint32_t)(a_row * BFS + a_col) * 2;
    const uint32_t aXT_base = smb + XTB_OFF + (uint32_t)(a_row * BFS + a_col) * 2;
    const uint32_t bWV_base = smb + WVB_OFF + (uint32_t)(b_row * BFS + b_col) * 2;
    const uint32_t bCH_base = smb + CTH_OFF + (uint32_t)(b_row * BFS + b_col) * 2;
    const uint32_t bCL_base = smb + CTL_OFF + (uint32_t)(b_row * BFS + b_col) * 2;

    const int r0 = lane >> 2, c0 = 2 * (lane & 3);

    float breg[16];   // logits carried across iterations (fragment order)

    // ---- stage bf16 X tile (once) ----
    {
        const float4* Xb = (const float4*)(X + ((size_t)b * IC + i0) * ID);
        uint32_t* dst = (uint32_t*)(smc + XSB_OFF);
        for (int u = t; u < TI * 32; u += 256) {
            const int r = u >> 5, q = u & 31;
            const float4 v = Xb[r * 32 + q];
            dst[r * (BFS / 2) + 2 * q]     = cvt2(v.x, v.y);
            dst[r * (BFS / 2) + 2 * q + 1] = cvt2(v.z, v.w);
        }
    }
    __syncthreads();
    // ---- in-smem bf16 transpose xs_hi -> xsT_hi (once) ----
    {
        const __nv_bfloat16* s = (const __nv_bfloat16*)(smc + XSB_OFF);
        __nv_bfloat16* d = (__nv_bfloat16*)(smc + XTB_OFF);
        for (int u = t; u < TI * ID; u += 256)
            d[(u >> 7) * BFS + (u & 127)] = s[(u & 127) * BFS + (u >> 7)];
    }
    __syncthreads();

    // ================= 3 routing iterations =================
    for (int iter = 0; iter < 3; iter++) {
        if (iter == 0) {
            const float* Pb = B0 + (size_t)b * NC * IC + i0;
            for (int u = t; u < NC * TI; u += 256) {
                const int n = u >> 7, i = u & 127;
                cs[i * CST + n] = Pb[(size_t)n * IC + i];
            }
            __syncthreads();
        } else {
            if (iter == 1) {
                const float* Pb = B0 + (size_t)b * NC * IC + i0;
                for (int u = t; u < NC * TI; u += 256) {
                    const int n = u >> 7, i = u & 127;
                    cs[i * CST + n] = Pb[(size_t)n * IC + i];
                }
                __syncthreads();
            }

            // ---- phase 1 MMA: uv[i][n] = sum_d x[i][d] * wv[n][d] ----
            float acc[4][4];
#pragma unroll
            for (int k = 0; k < 4; k++)
#pragma unroll
                for (int j = 0; j < 4; j++) acc[k][j] = 0.f;

#pragma unroll
            for (int kk = 0; kk < 8; kk++) {
                uint32_t a0, a1, a2, a3;
                ldsm_x4(a0, a1, a2, a3, aXS_base + kk * 32);
#pragma unroll
                for (int np = 0; np < 2; np++) {
                    uint32_t b0r, b1r, b2r, b3r;
                    ldsm_x4(b0r, b1r, b2r, b3r, bWV_base + np * (16 * BFS * 2) + kk * 32);
                    mma_bf16(acc[2 * np],     a0, a1, a2, a3, b0r, b1r);
                    mma_bf16(acc[2 * np + 1], a0, a1, a2, a3, b2r, b3r);
                }
            }

            // epilogue: b_new = b_prev + uv (registers/smem only)
#pragma unroll
            for (int nt = 0; nt < 4; nt++)
#pragma unroll
                for (int rr = 0; rr < 2; rr++) {
                    const int i_loc = m0 + r0 + rr * 8;
#pragma unroll
                    for (int cc = 0; cc < 2; cc++) {
                        const int n = nt * 8 + c0 + cc;
                        const int idx = nt * 4 + rr * 2 + cc;
                        const float prev = (iter == 1) ? cs[i_loc * CST + n] : breg[idx];
                        const float nb = prev + acc[nt][rr * 2 + cc];
                        breg[idx] = nb;
                        cs[i_loc * CST + n] = nb;
                    }
                }
            __syncthreads();

            // iter2: stage xsT_lo into the (now free) xs_hi region
            if (iter == 2) {
                const float* Xg = X + ((size_t)b * IC + i0) * ID;
                __nv_bfloat16* xlo = (__nv_bfloat16*)(smc + XSB_OFF);
                const __nv_bfloat16* xhiT = (const __nv_bfloat16*)(smc + XTB_OFF);
                for (int u = t; u < TI * ID; u += 256) {
                    const int i = u >> 7, d = u & 127;
                    const float hi = __bfloat162float(xhiT[d * BFS + i]);
                    xlo[d * BFS + i] = __float2bfloat16(Xg[(size_t)i * ID + d] - hi);
                }
            }
        }

        // ---- softmax over n (2 threads per i-row) + bf16 cT writes ----
        {
            const int i = t >> 1;
            const int h = (t & 1) << 4;
            float* row = cs + i * CST + h;
            float s = 0.f;
            if (iter < 2) {
#pragma unroll
                for (int n = 0; n < 16; n++) {
                    const float e = fexp(row[n]);
                    row[n] = e;
                    s += e;
                }
            } else {
                float m = row[0];
#pragma unroll
                for (int n = 1; n < 16; n++) m = fmaxf(m, row[n]);
                m = fmaxf(m, __shfl_xor_sync(0xffffffffu, m, 1));
#pragma unroll
                for (int n = 0; n < 16; n++) {
                    const float e = __expf(row[n] - m);
                    row[n] = e;
                    s += e;
                }
            }
            s += __shfl_xor_sync(0xffffffffu, s, 1);
            const float r = __fdividef(1.f, s);
            __nv_bfloat16* cth = (__nv_bfloat16*)(smc + CTH_OFF);
            __nv_bfloat16* ctl = (__nv_bfloat16*)(smc + CTL_OFF);
#pragma unroll
            for (int n = 0; n < 16; n++) {
                const float c = row[n] * r;
                const __nv_bfloat16 chb = __float2bfloat16(c);
                cth[(h + n) * BFS + i] = chb;
                if (iter == 2)
                    ctl[(h + n) * BFS + i] = __float2bfloat16(c - __bfloat162float(chb));
            }
        }
        __syncthreads();

        // ---- phase 3 MMA: Ysm[n][d] = sum_i xT[d][i] * c[i][n] (local smem) ----
        {
            float acc[4][4];
#pragma unroll
            for (int k = 0; k < 4; k++)
#pragma unroll
                for (int j = 0; j < 4; j++) acc[k][j] = 0.f;

            if (iter < 2) {
#pragma unroll
                for (int kk = 0; kk < 8; kk++) {
                    uint32_t a0, a1, a2, a3;
                    ldsm_x4(a0, a1, a2, a3, aXT_base + kk * 32);
#pragma unroll
                    for (int np = 0; np < 2; np++) {
                        uint32_t b0r, b1r, b2r, b3r;
                        ldsm_x4(b0r, b1r, b2r, b3r, bCH_base + np * (16 * BFS * 2) + kk * 32);
                        mma_bf16(acc[2 * np],     a0, a1, a2, a3, b0r, b1r);
                        mma_bf16(acc[2 * np + 1], a0, a1, a2, a3, b2r, b3r);
                    }
                }
            } else {
                // 3-term split: x_hi*c_hi + x_hi*c_lo + x_lo*c_hi (fp32 accum)
#pragma unroll
                for (int kk = 0; kk < 8; kk++) {
                    uint32_t h0, h1, h2, h3, l0, l1, l2, l3;
                    ldsm_x4(h0, h1, h2, h3, aXT_base + kk * 32);
                    ldsm_x4(l0, l1, l2, l3, aXS_base + kk * 32);   // xsT_lo
#pragma unroll
                    for (int np = 0; np < 2; np++) {
                        uint32_t bh0, bh1, bh2, bh3, bl0, bl1, bl2, bl3;
                        ldsm_x4(bh0, bh1, bh2, bh3, bCH_base + np * (16 * BFS * 2) + kk * 32);
                        ldsm_x4(bl0, bl1, bl2, bl3, bCL_base + np * (16 * BFS * 2) + kk * 32);
                        mma_bf16(acc[2 * np],     h0, h1, h2, h3, bh0, bh1);
                        mma_bf16(acc[2 * np],     h0, h1, h2, h3, bl0, bl1);
                        mma_bf16(acc[2 * np],     l0, l1, l2, l3, bh0, bh1);
                        mma_bf16(acc[2 * np + 1], h0, h1, h2, h3, bh2, bh3);
                        mma_bf16(acc[2 * np + 1], h0, h1, h2, h3, bl2, bl3);
                        mma_bf16(acc[2 * np + 1], l0, l1, l2, l3, bh2, bh3);
                    }
                }
            }

            float* Ysm = (float*)(smc + CS_OFF);   // aliases cs (logits live in breg)
#pragma unroll
            for (int nt = 0; nt < 4; nt++)
#pragma unroll
                for (int rr = 0; rr < 2; rr++) {
                    const int d_loc = m0 + r0 + rr * 8;
#pragma unroll
                    for (int cc = 0; cc < 2; cc++) {
                        const int n = nt * 8 + c0 + cc;
                        Ysm[n * YST + d_loc] = acc[nt][rr * 2 + cc];
                    }
                }
        }
        __syncthreads();
        CLUSTER_SYNC();   // Ysm visible cluster-wide

        // ======== svwv: warp w -> capsule n = tt*8 + w (DSMEM reduce) ========
        {
            const int nl = tt * 8 + w;
            const int d0 = lane * 4;
            const uint32_t laddr = smb + CS_OFF + (uint32_t)(nl * YST + d0) * 4;
            float4 yacc = make_float4(0.f, 0.f, 0.f, 0.f);
#pragma unroll
            for (int rr = 0; rr < CLUSTER; rr++) {
                const float4 v = ld_dsmem4(mapa_u32(laddr, (uint32_t)rr));
                yacc.x += v.x; yacc.y += v.y; yacc.z += v.z; yacc.w += v.w;
            }
            float* Yred = (float*)(smc + CTL_OFF);          // [8][132] scratch
            *(float4*)(Yred + w * YST + d0) = yacc;
            __syncwarp();

            // s-dot: lane = output c; W rows coalesced from L2
            const float* Wn = W + (size_t)nl * ID * DC;
            float s = 0.f;
#pragma unroll 8
            for (int d = 0; d < ID; d++)
                s = fmaf(Yred[w * YST + d], Wn[d * DC + lane], s);

            float snorm = s * s;
#pragma unroll
            for (int o = 16; o; o >>= 1) snorm += __shfl_xor_sync(0xffffffffu, snorm, o);
            const float v = s * snorm / ((1.f + snorm) * (sqrtf(snorm) + 1e-8f));

            if (iter == 2) {
                OUT[(((size_t)b) * NC + nl) * DC + lane] = v;
            } else {
                float* vsm = (float*)(smc + CTL_OFF + 8 * YST * 4);   // [8][32]
                vsm[w * 32 + lane] = v;
                __syncwarp();

                // wv[nl][d] = sum_c W[nl][d][c] * v[c] -> local bf16 rows
                __nv_bfloat16* wvb = (__nv_bfloat16*)(smc + WVB_OFF);
#pragma unroll
                for (int k = 0; k < 4; k++) {
                    const int d = 32 * k + lane;
                    const float4* Wr = (const float4*)(Wn + d * DC);
                    float a = 0.f;
#pragma unroll
                    for (int q = 0; q < 8; q++) {
                        const float4 ww = Wr[q];
                        const float4 vv = *(const float4*)(vsm + w * 32 + q * 4);
                        a = fmaf(ww.x, vv.x, a);
                        a = fmaf(ww.y, vv.y, a);
                        a = fmaf(ww.z, vv.z, a);
                        a = fmaf(ww.w, vv.w, a);
                    }
                    wvb[nl * BFS + d] = __float2bfloat16(a);
                }
            }
        }
        __syncthreads();
        CLUSTER_SYNC();   // wv rows visible; Ysm reads complete (safe to reuse cs)

        // gather peer wv rows (24 rows x 128 bf16) via DSMEM
        if (iter < 2) {
            for (int u = t; u < 3 * 8 * 64; u += 256) {
                const int rr = (tt + 1 + (u >> 9)) & 3;
                const int row = rr * 8 + ((u >> 6) & 7);
                const int c = u & 63;
                const uint32_t off = (uint32_t)(WVB_OFF + row * (BFS * 2) + c * 4);
                *(uint32_t*)(smc + off) = ld_dsmem1(mapa_u32(smb + off, (uint32_t)rr));
            }
            __syncthreads();
        }
    }
}

// ============================================================
// launch
// ============================================================
extern "C" void kernel_launch(void* const* d_in, const int* in_sizes, int n_in,
                              void* d_out, int out_size) {
    const float *X = nullptr, *Wp = nullptr, *B0 = nullptr;
    for (int i = 0; i < n_in; i++) {
        if      (in_sizes[i] == B_ * IC * ID) X  = (const float*)d_in[i];
        else if (in_sizes[i] == NC * ID * DC) Wp = (const float*)d_in[i];
        else if (in_sizes[i] == B_ * NC * IC) B0 = (const float*)d_in[i];
    }
    float* OUT = (float*)d_out;

    cudaFuncSetAttribute(k_mega,
                         cudaFuncAttributeMaxDynamicSharedMemorySize, SMEM_BYTES);

    k_mega<<<NBLK, 256, SMEM_BYTES>>>(X, Wp, B0, OUT);
}